// round 2
// baseline (speedup 1.0000x reference)
#include <cuda_runtime.h>

// Problem constants
#define B_     64
#define NM_    32
#define NS_    32
#define K_     3
#define HID_   64
#define NLAYER_ 4
#define S_     2048      // B*NS
#define P_     6         // K!
#define ROWS_  192       // NM*P

// itertools.permutations(range(3)) order; allperm[k][p] = c_perm[p][k]
__constant__ int c_perm[6][3] = {
    {0,1,2},{0,2,1},{1,0,2},{1,2,0},{2,0,1},{2,1,0}
};

// segment-max accumulator (nonneg floats -> int-ordered compare works)
__device__ int g_pooled[B_ * HID_];

// ---- shared memory layout (in floats) ----
#define OFF_A   0                      // 32x32 adjacency          (1024)
#define OFF_H   1024                   // h: 192 rows x 64          (12288)
#define OFF_M   (OFF_H + 12288)        // m buffer: 192 x 64        (12288)
#define OFF_W1  (OFF_M + 12288)        // W1 64x64                  (4096)
#define OFF_W2  (OFF_W1 + 4096)        // W2 64x64                  (4096)
#define OFF_B1  (OFF_W2 + 4096)        // b1                        (64)
#define OFF_B2  (OFF_B1 + 64)          // b2                        (64)
#define OFF_G   (OFF_B2 + 64)          // ln gamma                  (64)
#define OFF_BE  (OFF_G + 64)           // ln beta                   (64)
#define OFF_TS  (OFF_BE + 64)          // per-warp scratch 8x256    (2048)
#define OFF_SS  (OFF_TS + 2048)        // node-sum vector           (64)
#define SMEM_FLOATS (OFF_SS + 64)
#define SMEM_BYTES  (SMEM_FLOATS * 4)  // 144640 B

__global__ void __launch_bounds__(256, 1) zero_pooled_k() {
    int i = blockIdx.x * blockDim.x + threadIdx.x;
    if (i < B_ * HID_) g_pooled[i] = 0;
}

__global__ void __launch_bounds__(256, 1) idmpnn_main(
    const int*   __restrict__ x,        // (B, NM, 1)
    const float* __restrict__ subadj,   // (B, NM, NM)
    const int*   __restrict__ subgs,    // (S, K)
    const int*   __restrict__ num_node, // (B,)
    const float* __restrict__ idemb,    // (5, 64)
    const float* __restrict__ node_emb, // (101, 64)
    const float* __restrict__ W1g,      // (4,64,64)
    const float* __restrict__ b1g,      // (4,64)
    const float* __restrict__ W2g,      // (4,64,64)
    const float* __restrict__ b2g,      // (4,64)
    const float* __restrict__ gg,       // (4,64)
    const float* __restrict__ beg,      // (4,64)
    const float* __restrict__ s1W, const float* __restrict__ s1b,
    const float* __restrict__ s2W, const float* __restrict__ s2b)
{
    extern __shared__ float sm[];
    const int s    = blockIdx.x;
    const int b    = s >> 5;           // graph id (NS=32)
    const int tid  = threadIdx.x;
    const int warp = tid >> 5;
    const int lane = tid & 31;

    // ---- load adjacency ----
    {
        const float4* Ag = (const float4*)(subadj + b * 1024);
        float4* As = (float4*)(sm + OFF_A);
        #pragma unroll
        for (int i = tid; i < 256; i += 256) As[i] = Ag[i];
    }

    // ---- build initial H: node_emb gather, labeled-node perm-id multiply ----
    const int sg0 = subgs[3 * s + 0];
    const int sg1 = subgs[3 * s + 1];
    const int sg2 = subgs[3 * s + 2];
    for (int e = tid; e < 12288; e += 256) {
        int node = e / 384;
        int rp   = e - node * 384;
        int p    = rp >> 6;
        int d    = rp & 63;
        float v = node_emb[x[b * 32 + node] * 64 + d];
        int k = (node == sg0) ? 0 : (node == sg1) ? 1 : (node == sg2) ? 2 : -1;
        if (k >= 0) v *= idemb[c_perm[p][k] * 64 + d];
        sm[OFF_H + e] = v;
    }
    __syncthreads();

    // ================= layer loop =================
    for (int l = 0; l < NLAYER_; l++) {
        // load this layer's weights into smem
        {
            const float4* w1v = (const float4*)(W1g + l * 4096);
            const float4* w2v = (const float4*)(W2g + l * 4096);
            float4* W1s = (float4*)(sm + OFF_W1);
            float4* W2s = (float4*)(sm + OFF_W2);
            #pragma unroll
            for (int i = tid; i < 1024; i += 256) { W1s[i] = w1v[i]; W2s[i] = w2v[i]; }
            if (tid < 64) {
                sm[OFF_B1 + tid] = b1g[l * 64 + tid];
                sm[OFF_B2 + tid] = b2g[l * 64 + tid];
                sm[OFF_G  + tid] = gg [l * 64 + tid];
                sm[OFF_BE + tid] = beg[l * 64 + tid];
            }
        }
        __syncthreads();

        // ---- phase 1: M = A @ H  (block-diag GEMM, 8-row x 2-dim register tile)
        #pragma unroll
        for (int q = 0; q < 3; q++) {
            int tt = warp + 8 * q;          // 24 tasks: (p, i-block)
            int p  = tt >> 2;
            int i0 = (tt & 3) * 8;
            float acc0[8], acc1[8];
            #pragma unroll
            for (int ii = 0; ii < 8; ii++) { acc0[ii] = 0.f; acc1[ii] = 0.f; }
            #pragma unroll
            for (int j = 0; j < 32; j += 4) {
                float av[8][4];
                #pragma unroll
                for (int ii = 0; ii < 8; ii++)
                    *(float4*)av[ii] = *(const float4*)&sm[OFF_A + (i0 + ii) * 32 + j];
                #pragma unroll
                for (int jj = 0; jj < 4; jj++) {
                    float h0 = sm[OFF_H + ((j + jj) * 6 + p) * 64 + lane];
                    float h1 = sm[OFF_H + ((j + jj) * 6 + p) * 64 + lane + 32];
                    #pragma unroll
                    for (int ii = 0; ii < 8; ii++) {
                        acc0[ii] += av[ii][jj] * h0;
                        acc1[ii] += av[ii][jj] * h1;
                    }
                }
            }
            #pragma unroll
            for (int ii = 0; ii < 8; ii++) {
                int row = (i0 + ii) * 6 + p;
                sm[OFF_M + row * 64 + lane]      = acc0[ii];
                sm[OFF_M + row * 64 + lane + 32] = acc1[ii];
            }
        }
        __syncthreads();

        // ---- phase 2: per-row MLP + LayerNorm + residual (4-row register tile)
        float* Ts = sm + OFF_TS + warp * 256;
        #pragma unroll
        for (int g4 = 0; g4 < 6; g4++) {
            int r0 = warp * 24 + g4 * 4;
            float a0[4], a1[4];
            #pragma unroll
            for (int r = 0; r < 4; r++) { a0[r] = 0.f; a1[r] = 0.f; }
            #pragma unroll
            for (int d = 0; d < 64; d += 4) {
                float mv[4][4];
                #pragma unroll
                for (int r = 0; r < 4; r++)
                    *(float4*)mv[r] = *(const float4*)&sm[OFF_M + (r0 + r) * 64 + d];
                #pragma unroll
                for (int jj = 0; jj < 4; jj++) {
                    float w1a = sm[OFF_W1 + (d + jj) * 64 + lane];
                    float w1b = sm[OFF_W1 + (d + jj) * 64 + lane + 32];
                    #pragma unroll
                    for (int r = 0; r < 4; r++) {
                        a0[r] += mv[r][jj] * w1a;
                        a1[r] += mv[r][jj] * w1b;
                    }
                }
            }
            #pragma unroll
            for (int r = 0; r < 4; r++) {
                Ts[r * 64 + lane]      = fmaxf(a0[r] + sm[OFF_B1 + lane], 0.f);
                Ts[r * 64 + lane + 32] = fmaxf(a1[r] + sm[OFF_B1 + lane + 32], 0.f);
            }
            __syncwarp();
            float u0[4], u1[4];
            #pragma unroll
            for (int r = 0; r < 4; r++) { u0[r] = 0.f; u1[r] = 0.f; }
            #pragma unroll
            for (int d = 0; d < 64; d += 4) {
                float tv[4][4];
                #pragma unroll
                for (int r = 0; r < 4; r++)
                    *(float4*)tv[r] = *(const float4*)&Ts[r * 64 + d];
                #pragma unroll
                for (int jj = 0; jj < 4; jj++) {
                    float w2a = sm[OFF_W2 + (d + jj) * 64 + lane];
                    float w2b = sm[OFF_W2 + (d + jj) * 64 + lane + 32];
                    #pragma unroll
                    for (int r = 0; r < 4; r++) {
                        u0[r] += tv[r][jj] * w2a;
                        u1[r] += tv[r][jj] * w2b;
                    }
                }
            }
            #pragma unroll
            for (int r = 0; r < 4; r++) {
                float z0 = u0[r] + sm[OFF_B2 + lane];
                float z1 = u1[r] + sm[OFF_B2 + lane + 32];
                float sum = z0 + z1;
                #pragma unroll
                for (int o = 16; o; o >>= 1) sum += __shfl_xor_sync(0xffffffffu, sum, o);
                float mean = sum * (1.f / 64.f);
                float d0 = z0 - mean, d1 = z1 - mean;
                float vs = d0 * d0 + d1 * d1;
                #pragma unroll
                for (int o = 16; o; o >>= 1) vs += __shfl_xor_sync(0xffffffffu, vs, o);
                float rstd = rsqrtf(vs * (1.f / 64.f) + 1e-5f);
                float o0 = fmaxf(d0 * rstd * sm[OFF_G + lane]      + sm[OFF_BE + lane],      0.f);
                float o1 = fmaxf(d1 * rstd * sm[OFF_G + lane + 32] + sm[OFF_BE + lane + 32], 0.f);
                sm[OFF_H + (r0 + r) * 64 + lane]      += o0;
                sm[OFF_H + (r0 + r) * 64 + lane + 32] += o1;
            }
            __syncwarp();
        }
        __syncthreads();
    }

    // ================= epilogue =================
    // load set-MLP weights (reuse W1/W2 buffers)
    {
        const float4* w1v = (const float4*)s1W;
        const float4* w2v = (const float4*)s2W;
        float4* W1s = (float4*)(sm + OFF_W1);
        float4* W2s = (float4*)(sm + OFF_W2);
        #pragma unroll
        for (int i = tid; i < 1024; i += 256) { W1s[i] = w1v[i]; W2s[i] = w2v[i]; }
        if (tid < 64) { sm[OFF_B1 + tid] = s1b[tid]; sm[OFF_B2 + tid] = s2b[tid]; }
    }
    // zero padded-node rows (i >= num_node[b])
    const int nn = num_node[b];
    for (int e = nn * 384 + tid; e < 12288; e += 256) sm[OFF_H + e] = 0.f;
    __syncthreads();

    // mean over perms -> M[i*64+d]
    for (int e = tid; e < 2048; e += 256) {
        int i = e >> 6, d = e & 63;
        float acc = 0.f;
        #pragma unroll
        for (int p = 0; p < 6; p++) acc += sm[OFF_H + (i * 6 + p) * 64 + d];
        sm[OFF_M + e] = acc * (1.f / 6.f);
    }
    __syncthreads();

    // set1 MLP over 32 node rows (4 rows/warp) + per-warp node-sum partials
    {
        int r0 = warp * 4;
        float a0[4], a1[4];
        #pragma unroll
        for (int r = 0; r < 4; r++) { a0[r] = 0.f; a1[r] = 0.f; }
        #pragma unroll
        for (int d = 0; d < 64; d += 4) {
            float mv[4][4];
            #pragma unroll
            for (int r = 0; r < 4; r++)
                *(float4*)mv[r] = *(const float4*)&sm[OFF_M + (r0 + r) * 64 + d];
            #pragma unroll
            for (int jj = 0; jj < 4; jj++) {
                float w1a = sm[OFF_W1 + (d + jj) * 64 + lane];
                float w1b = sm[OFF_W1 + (d + jj) * 64 + lane + 32];
                #pragma unroll
                for (int r = 0; r < 4; r++) {
                    a0[r] += mv[r][jj] * w1a;
                    a1[r] += mv[r][jj] * w1b;
                }
            }
        }
        float p0 = 0.f, p1 = 0.f;
        #pragma unroll
        for (int r = 0; r < 4; r++) {
            p0 += fmaxf(a0[r] + sm[OFF_B1 + lane], 0.f);
            p1 += fmaxf(a1[r] + sm[OFF_B1 + lane + 32], 0.f);
        }
        sm[OFF_TS + warp * 64 + lane]      = p0;
        sm[OFF_TS + warp * 64 + lane + 32] = p1;
    }
    __syncthreads();
    if (tid < 64) {
        float ss = 0.f;
        #pragma unroll
        for (int w = 0; w < 8; w++) ss += sm[OFF_TS + w * 64 + tid];
        sm[OFF_SS + tid] = ss;
    }
    __syncthreads();

    // set2 MLP on the summed vector + atomic segment-max
    if (warp == 0) {
        float a0 = 0.f, a1 = 0.f;
        #pragma unroll
        for (int d = 0; d < 64; d++) {
            float v = sm[OFF_SS + d];
            a0 += v * sm[OFF_W2 + d * 64 + lane];
            a1 += v * sm[OFF_W2 + d * 64 + lane + 32];
        }
        float t0 = fmaxf(a0 + sm[OFF_B2 + lane], 0.f);
        float t1 = fmaxf(a1 + sm[OFF_B2 + lane + 32], 0.f);
        atomicMax(&g_pooled[b * 64 + lane],      __float_as_int(t0));
        atomicMax(&g_pooled[b * 64 + lane + 32], __float_as_int(t1));
    }
}

__global__ void __launch_bounds__(64, 1) finalize_k(
    const float* __restrict__ outW, const float* __restrict__ outb,
    float* __restrict__ out)
{
    int b = blockIdx.x;
    int d = threadIdx.x;
    float v = __int_as_float(g_pooled[b * 64 + d]) * outW[d];
    #pragma unroll
    for (int o = 16; o; o >>= 1) v += __shfl_xor_sync(0xffffffffu, v, o);
    __shared__ float red[2];
    if ((d & 31) == 0) red[d >> 5] = v;
    __syncthreads();
    if (d == 0) out[b] = red[0] + red[1] + outb[0];
}

extern "C" void kernel_launch(void* const* d_in, const int* in_sizes, int n_in,
                              void* d_out, int out_size)
{
    const int*   x        = (const int*)  d_in[0];
    const float* subadj   = (const float*)d_in[1];
    const int*   subgs    = (const int*)  d_in[2];
    const int*   num_node = (const int*)  d_in[3];
    // d_in[4] = num_subg (unused: all graphs have NS subgraphs)
    const float* idemb    = (const float*)d_in[5];
    const float* node_emb = (const float*)d_in[6];
    const float* W1       = (const float*)d_in[7];
    const float* b1       = (const float*)d_in[8];
    const float* W2       = (const float*)d_in[9];
    const float* b2       = (const float*)d_in[10];
    const float* g        = (const float*)d_in[11];
    const float* be       = (const float*)d_in[12];
    const float* s1W      = (const float*)d_in[13];
    const float* s1b      = (const float*)d_in[14];
    const float* s2W      = (const float*)d_in[15];
    const float* s2b      = (const float*)d_in[16];
    const float* outW     = (const float*)d_in[17];
    const float* outb     = (const float*)d_in[18];

    cudaFuncSetAttribute(idmpnn_main,
                         cudaFuncAttributeMaxDynamicSharedMemorySize, SMEM_BYTES);

    zero_pooled_k<<<(B_ * HID_ + 255) / 256, 256>>>();
    idmpnn_main<<<S_, 256, SMEM_BYTES>>>(
        x, subadj, subgs, num_node, idemb, node_emb,
        W1, b1, W2, b2, g, be, s1W, s1b, s2W, s2b);
    finalize_k<<<B_, 64>>>(outW, outb, (float*)d_out);
}

// round 4
// speedup vs baseline: 1.8661x; 1.8661x over previous
#include <cuda_runtime.h>

// Problem constants
#define B_      64
#define NM_     32
#define NS_     32
#define K_      3
#define HID_    64
#define NLAYER_ 4
#define S_      2048     // B*NS
#define P_      6        // K!
#define ROWS_   192      // NM*P
#define NTHR_   512      // 16 warps

// itertools.permutations(range(3)); allperm[k][p] = c_perm[p][k]
__constant__ int c_perm[6][3] = {
    {0,1,2},{0,2,1},{1,0,2},{1,2,0},{2,0,1},{2,1,0}
};

// per-subgraph post-set2 vectors (S, 64)
__device__ float g_subg[S_ * HID_];

// ---- shared memory layout (floats) ----
#define OFF_A    0                       // 32x32 adjacency       (1024)
#define OFF_HA   1024                    // H ping                 (12288)
#define OFF_HB   (OFF_HA + 12288)        // H pong                 (12288)
#define OFF_WB0  (OFF_HB + 12288)        // weight buffer 0        (8448)
#define OFF_WB1  (OFF_WB0 + 8448)        // weight buffer 1        (8448)
#define OFF_TS   (OFF_WB1 + 8448)        // per-warp staging 16x256 (4096)
#define OFF_SS   (OFF_TS + 4096)         // node-sum vector        (64)
#define SMEM_FLOATS (OFF_SS + 64)
#define SMEM_BYTES  (SMEM_FLOATS * 4)    // 186,624 B

// offsets inside a weight buffer
#define WOFF_W1  0
#define WOFF_W2  4096
#define WOFF_B1  8192
#define WOFF_B2  8256
#define WOFF_G   8320
#define WOFF_BE  8384

__device__ __forceinline__ void load_layer_weights(
    float* dst, int tid,
    const float* __restrict__ W1g, const float* __restrict__ b1g,
    const float* __restrict__ W2g, const float* __restrict__ b2g,
    const float* __restrict__ gg,  const float* __restrict__ beg, int l)
{
    const float4* w1v = (const float4*)(W1g + l * 4096);
    const float4* w2v = (const float4*)(W2g + l * 4096);
    float4* d1 = (float4*)(dst + WOFF_W1);
    float4* d2 = (float4*)(dst + WOFF_W2);
    #pragma unroll
    for (int i = tid; i < 1024; i += NTHR_) { d1[i] = w1v[i]; d2[i] = w2v[i]; }
    if (tid < 64) {
        dst[WOFF_B1 + tid] = b1g[l * 64 + tid];
        dst[WOFF_B2 + tid] = b2g[l * 64 + tid];
        dst[WOFF_G  + tid] = gg [l * 64 + tid];
        dst[WOFF_BE + tid] = beg[l * 64 + tid];
    }
}

__global__ void __launch_bounds__(NTHR_, 1) idmpnn_main(
    const int*   __restrict__ x,        // (B, NM, 1)
    const float* __restrict__ subadj,   // (B, NM, NM)
    const int*   __restrict__ subgs,    // (S, K)
    const int*   __restrict__ num_node, // (B,)  (padded rows handled; bias=0 makes them inert)
    const float* __restrict__ idemb,    // (5, 64)
    const float* __restrict__ node_emb, // (101, 64)
    const float* __restrict__ W1g, const float* __restrict__ b1g,
    const float* __restrict__ W2g, const float* __restrict__ b2g,
    const float* __restrict__ gg,  const float* __restrict__ beg,
    const float* __restrict__ s1W, const float* __restrict__ s1b,
    const float* __restrict__ s2W, const float* __restrict__ s2b)
{
    extern __shared__ float sm[];
    const int s    = blockIdx.x;
    const int b    = s >> 5;            // graph id (NS=32)
    const int tid  = threadIdx.x;
    const int warp = tid >> 5;
    const int lane = tid & 31;

    // ---- adjacency ----
    if (tid < 256) {
        ((float4*)(sm + OFF_A))[tid] = ((const float4*)(subadj + b * 1024))[tid];
    }
    // ---- layer-0 weights into WB0 ----
    load_layer_weights(sm + OFF_WB0, tid, W1g, b1g, W2g, b2g, gg, beg, 0);

    // ---- initial H (into HA): node_emb gather + labeled perm-id multiply ----
    {
        const int sg0 = subgs[3 * s + 0];
        const int sg1 = subgs[3 * s + 1];
        const int sg2 = subgs[3 * s + 2];
        for (int e = tid; e < 12288; e += NTHR_) {
            int node = e / 384;
            int rp   = e - node * 384;
            int p    = rp >> 6;
            int d    = rp & 63;
            float v = node_emb[x[b * 32 + node] * 64 + d];
            int k = (node == sg0) ? 0 : (node == sg1) ? 1 : (node == sg2) ? 2 : -1;
            if (k >= 0) v *= idemb[c_perm[p][k] * 64 + d];
            sm[OFF_HA + e] = v;
        }
    }
    __syncthreads();

    float* Ts = sm + OFF_TS + warp * 256;   // private 4x64 staging
    int srcO = OFF_HA, dstO = OFF_HB;

    // ================= layer loop (1 barrier per layer) =================
    for (int l = 0; l < NLAYER_; l++) {
        const float* W = sm + ((l & 1) ? OFF_WB1 : OFF_WB0);
        float* Wnext = sm + (((l + 1) & 1) ? OFF_WB1 : OFF_WB0);

        // prefetch next weights into the idle buffer
        if (l < NLAYER_ - 1) {
            load_layer_weights(Wnext, tid, W1g, b1g, W2g, b2g, gg, beg, l + 1);
        } else {
            // set-MLP weights for the epilogue
            const float4* w1v = (const float4*)s1W;
            const float4* w2v = (const float4*)s2W;
            float4* d1 = (float4*)(Wnext + WOFF_W1);
            float4* d2 = (float4*)(Wnext + WOFF_W2);
            #pragma unroll
            for (int i = tid; i < 1024; i += NTHR_) { d1[i] = w1v[i]; d2[i] = w2v[i]; }
            if (tid < 64) {
                Wnext[WOFF_B1 + tid] = s1b[tid];
                Wnext[WOFF_B2 + tid] = s2b[tid];
            }
        }

        const float* src = sm + srcO;
        float*       dst = sm + dstO;

        // 48 tasks of (perm p, 4-row block); 3 per warp, fused mp+MLP+LN+residual
        #pragma unroll
        for (int q = 0; q < 3; q++) {
            const int t  = warp * 3 + q;
            const int p  = t >> 3;
            const int i0 = (t & 7) * 4;

            // ---- m = A @ H for 4 rows ----
            float acc0[4], acc1[4];
            #pragma unroll
            for (int r = 0; r < 4; r++) { acc0[r] = 0.f; acc1[r] = 0.f; }
            #pragma unroll
            for (int j = 0; j < 32; j += 4) {
                float av[4][4];
                #pragma unroll
                for (int r = 0; r < 4; r++)
                    *(float4*)av[r] = *(const float4*)&sm[OFF_A + (i0 + r) * 32 + j];
                #pragma unroll
                for (int jj = 0; jj < 4; jj++) {
                    float h0 = src[((j + jj) * 6 + p) * 64 + lane];
                    float h1 = src[((j + jj) * 6 + p) * 64 + lane + 32];
                    #pragma unroll
                    for (int r = 0; r < 4; r++) {
                        acc0[r] += av[r][jj] * h0;
                        acc1[r] += av[r][jj] * h1;
                    }
                }
            }
            #pragma unroll
            for (int r = 0; r < 4; r++) {
                Ts[r * 64 + lane]      = acc0[r];
                Ts[r * 64 + lane + 32] = acc1[r];
            }
            __syncwarp();

            // ---- MLP layer 1 ----
            float a0[4], a1[4];
            #pragma unroll
            for (int r = 0; r < 4; r++) { a0[r] = 0.f; a1[r] = 0.f; }
            #pragma unroll
            for (int d = 0; d < 64; d += 4) {
                float mv[4][4];
                #pragma unroll
                for (int r = 0; r < 4; r++)
                    *(float4*)mv[r] = *(const float4*)&Ts[r * 64 + d];
                #pragma unroll
                for (int jj = 0; jj < 4; jj++) {
                    float wa = W[WOFF_W1 + (d + jj) * 64 + lane];
                    float wb = W[WOFF_W1 + (d + jj) * 64 + lane + 32];
                    #pragma unroll
                    for (int r = 0; r < 4; r++) {
                        a0[r] += mv[r][jj] * wa;
                        a1[r] += mv[r][jj] * wb;
                    }
                }
            }
            __syncwarp();
            #pragma unroll
            for (int r = 0; r < 4; r++) {
                Ts[r * 64 + lane]      = fmaxf(a0[r] + W[WOFF_B1 + lane], 0.f);
                Ts[r * 64 + lane + 32] = fmaxf(a1[r] + W[WOFF_B1 + lane + 32], 0.f);
            }
            __syncwarp();

            // ---- MLP layer 2 ----
            float u0[4], u1[4];
            #pragma unroll
            for (int r = 0; r < 4; r++) { u0[r] = 0.f; u1[r] = 0.f; }
            #pragma unroll
            for (int d = 0; d < 64; d += 4) {
                float tv[4][4];
                #pragma unroll
                for (int r = 0; r < 4; r++)
                    *(float4*)tv[r] = *(const float4*)&Ts[r * 64 + d];
                #pragma unroll
                for (int jj = 0; jj < 4; jj++) {
                    float wa = W[WOFF_W2 + (d + jj) * 64 + lane];
                    float wb = W[WOFF_W2 + (d + jj) * 64 + lane + 32];
                    #pragma unroll
                    for (int r = 0; r < 4; r++) {
                        u0[r] += tv[r][jj] * wa;
                        u1[r] += tv[r][jj] * wb;
                    }
                }
            }
            __syncwarp();

            // ---- batched LayerNorm + relu + residual (4 rows, ILP shuffles) ----
            float z0[4], z1[4], sum[4];
            #pragma unroll
            for (int r = 0; r < 4; r++) {
                z0[r] = u0[r] + W[WOFF_B2 + lane];
                z1[r] = u1[r] + W[WOFF_B2 + lane + 32];
                sum[r] = z0[r] + z1[r];
            }
            #pragma unroll
            for (int o = 16; o; o >>= 1) {
                #pragma unroll
                for (int r = 0; r < 4; r++)
                    sum[r] += __shfl_xor_sync(0xffffffffu, sum[r], o);
            }
            float var[4];
            #pragma unroll
            for (int r = 0; r < 4; r++) {
                float mean = sum[r] * (1.f / 64.f);
                z0[r] -= mean; z1[r] -= mean;
                var[r] = z0[r] * z0[r] + z1[r] * z1[r];
            }
            #pragma unroll
            for (int o = 16; o; o >>= 1) {
                #pragma unroll
                for (int r = 0; r < 4; r++)
                    var[r] += __shfl_xor_sync(0xffffffffu, var[r], o);
            }
            #pragma unroll
            for (int r = 0; r < 4; r++) {
                float rstd = rsqrtf(var[r] * (1.f / 64.f) + 1e-5f);
                float o0 = fmaxf(z0[r] * rstd * W[WOFF_G + lane]      + W[WOFF_BE + lane],      0.f);
                float o1 = fmaxf(z1[r] * rstd * W[WOFF_G + lane + 32] + W[WOFF_BE + lane + 32], 0.f);
                int row = (i0 + r) * 6 + p;
                dst[row * 64 + lane]      = src[row * 64 + lane]      + o0;
                dst[row * 64 + lane + 32] = src[row * 64 + lane + 32] + o1;
            }
        }
        __syncthreads();
        int tmp = srcO; srcO = dstO; dstO = tmp;
    }
    // final H is in HA (srcO == OFF_HA); set weights are in WB0

    const float* Wset = sm + OFF_WB0;

    // zero padded-node rows
    {
        const int nn = num_node[b];
        for (int e = nn * 384 + tid; e < 12288; e += NTHR_) sm[OFF_HA + e] = 0.f;
    }
    __syncthreads();

    // mean over perms -> HB[i*64+d]
    for (int e = tid; e < 2048; e += NTHR_) {
        int i = e >> 6, d = e & 63;
        float acc = 0.f;
        #pragma unroll
        for (int p = 0; p < 6; p++) acc += sm[OFF_HA + i * 384 + p * 64 + d];
        sm[OFF_HB + e] = acc * (1.f / 6.f);
    }
    __syncthreads();

    // set1 MLP over 32 node rows (2 per warp) + node-sum partials
    {
        const int r0 = warp * 2;
        float a0[2], a1[2];
        #pragma unroll
        for (int r = 0; r < 2; r++) { a0[r] = 0.f; a1[r] = 0.f; }
        #pragma unroll
        for (int d = 0; d < 64; d += 4) {
            float mv[2][4];
            #pragma unroll
            for (int r = 0; r < 2; r++)
                *(float4*)mv[r] = *(const float4*)&sm[OFF_HB + (r0 + r) * 64 + d];
            #pragma unroll
            for (int jj = 0; jj < 4; jj++) {
                float wa = Wset[WOFF_W1 + (d + jj) * 64 + lane];
                float wb = Wset[WOFF_W1 + (d + jj) * 64 + lane + 32];
                #pragma unroll
                for (int r = 0; r < 2; r++) {
                    a0[r] += mv[r][jj] * wa;
                    a1[r] += mv[r][jj] * wb;
                }
            }
        }
        float p0 = 0.f, p1 = 0.f;
        #pragma unroll
        for (int r = 0; r < 2; r++) {
            p0 += fmaxf(a0[r] + Wset[WOFF_B1 + lane],      0.f);
            p1 += fmaxf(a1[r] + Wset[WOFF_B1 + lane + 32], 0.f);
        }
        sm[OFF_TS + warp * 64 + lane]      = p0;
        sm[OFF_TS + warp * 64 + lane + 32] = p1;
    }
    __syncthreads();
    if (tid < 64) {
        float ss = 0.f;
        #pragma unroll
        for (int w = 0; w < 16; w++) ss += sm[OFF_TS + w * 64 + tid];
        sm[OFF_SS + tid] = ss;
    }
    __syncthreads();

    // set2 MLP on summed vector -> per-subgraph output
    if (warp == 0) {
        float a0 = 0.f, a1 = 0.f;
        #pragma unroll
        for (int d = 0; d < 64; d++) {
            float v = sm[OFF_SS + d];
            a0 += v * Wset[WOFF_W2 + d * 64 + lane];
            a1 += v * Wset[WOFF_W2 + d * 64 + lane + 32];
        }
        g_subg[s * 64 + lane]      = fmaxf(a0 + Wset[WOFF_B2 + lane],      0.f);
        g_subg[s * 64 + lane + 32] = fmaxf(a1 + Wset[WOFF_B2 + lane + 32], 0.f);
    }
}

__global__ void __launch_bounds__(64, 1) finalize_k(
    const float* __restrict__ outW, const float* __restrict__ outb,
    float* __restrict__ out)
{
    const int b = blockIdx.x;
    const int d = threadIdx.x;
    float m = g_subg[(b * 32) * 64 + d];
    #pragma unroll
    for (int ss = 1; ss < 32; ss++)
        m = fmaxf(m, g_subg[(b * 32 + ss) * 64 + d]);
    float v = m * outW[d];
    #pragma unroll
    for (int o = 16; o; o >>= 1) v += __shfl_xor_sync(0xffffffffu, v, o);
    __shared__ float red[2];
    if ((d & 31) == 0) red[d >> 5] = v;
    __syncthreads();
    if (d == 0) out[b] = red[0] + red[1] + outb[0];
}

extern "C" void kernel_launch(void* const* d_in, const int* in_sizes, int n_in,
                              void* d_out, int out_size)
{
    const int*   x        = (const int*)  d_in[0];
    const float* subadj   = (const float*)d_in[1];
    const int*   subgs    = (const int*)  d_in[2];
    const int*   num_node = (const int*)  d_in[3];
    // d_in[4] = num_subg (unused: all graphs have NS subgraphs)
    const float* idemb    = (const float*)d_in[5];
    const float* node_emb = (const float*)d_in[6];
    const float* W1       = (const float*)d_in[7];
    const float* b1       = (const float*)d_in[8];
    const float* W2       = (const float*)d_in[9];
    const float* b2       = (const float*)d_in[10];
    const float* g        = (const float*)d_in[11];
    const float* be       = (const float*)d_in[12];
    const float* s1W      = (const float*)d_in[13];
    const float* s1b      = (const float*)d_in[14];
    const float* s2W      = (const float*)d_in[15];
    const float* s2b      = (const float*)d_in[16];
    const float* outW     = (const float*)d_in[17];
    const float* outb     = (const float*)d_in[18];

    cudaFuncSetAttribute(idmpnn_main,
                         cudaFuncAttributeMaxDynamicSharedMemorySize, SMEM_BYTES);

    idmpnn_main<<<S_, NTHR_, SMEM_BYTES>>>(
        x, subadj, subgs, num_node, idemb, node_emb,
        W1, b1, W2, b2, g, be, s1W, s1b, s2W, s2b);
    finalize_k<<<B_, 64>>>(outW, outb, (float*)d_out);
}

// round 6
// speedup vs baseline: 1.8699x; 1.0021x over previous
#include <cuda_runtime.h>

// Problem constants
#define B_      64
#define NM_     32
#define NS_     32
#define K_      3
#define HID_    64
#define NLAYER_ 4
#define S_      2048     // B*NS
#define P_      6        // K!
#define ROWS_   192      // NM*P
#define NTHR_   512      // 16 warps

// itertools.permutations(range(3)); allperm[k][p] = c_perm[p][k]
__constant__ int c_perm[6][3] = {
    {0,1,2},{0,2,1},{1,0,2},{1,2,0},{2,0,1},{2,1,0}
};

// per-subgraph post-set2 vectors (S, 64) — logical dim order
__device__ float g_subg[S_ * HID_];

// ---- shared memory layout (floats) ----
// Feature dim stored PHYSICALLY INTERLEAVED: physical q holds logical
// d = (q>>1) + (q&1)*32, so lane L owns the packed pair at phys {2L, 2L+1}
// = logical {L, L+32}. Applies to H, Ts, W (N-cols), biases. Gamma/beta plain.
#define OFF_A    0                       // 32x32 adjacency        (1024)
#define OFF_HA   1024                    // H ping                 (12288)
#define OFF_HB   (OFF_HA + 12288)        // H pong                 (12288)
#define OFF_WB0  (OFF_HB + 12288)        // weight buffer 0        (8448)
#define OFF_WB1  (OFF_WB0 + 8448)        // weight buffer 1        (8448)
#define OFF_TS   (OFF_WB1 + 8448)        // per-warp staging 16x256 (4096)
#define OFF_SS   (OFF_TS + 4096)         // node-sum vector        (64)
#define SMEM_FLOATS (OFF_SS + 64)
#define SMEM_BYTES  (SMEM_FLOATS * 4)    // 186,624 B

// offsets inside a weight buffer (K-rows physically permuted, N-cols interleaved)
#define WOFF_W1  0
#define WOFF_W2  4096
#define WOFF_B1  8192
#define WOFF_B2  8256
#define WOFF_G   8320
#define WOFF_BE  8384

typedef unsigned long long ull;

__device__ __forceinline__ void ffma2(ull& d, ull a, ull b) {
    asm("fma.rn.f32x2 %0, %1, %2, %0;" : "+l"(d) : "l"(a), "l"(b));
}
__device__ __forceinline__ ull splat2(float v) {
    ull r;
    asm("mov.b64 %0, {%1, %1};" : "=l"(r) : "f"(v));
    return r;
}
__device__ __forceinline__ float2 unpk(ull v) {
    float2 f;
    asm("mov.b64 {%0, %1}, %2;" : "=f"(f.x), "=f"(f.y) : "l"(v));
    return f;
}
__device__ __forceinline__ int dlog(int q) { return (q >> 1) + ((q & 1) << 5); }

// load one layer's weights into smem, applying the interleave permutation:
//   dst[kq*64 + q] = W[dlog(kq)*64 + dlog(q)]
__device__ __forceinline__ void load_layer_weights(
    float* dst, int tid,
    const float* __restrict__ W1g, const float* __restrict__ b1g,
    const float* __restrict__ W2g, const float* __restrict__ b2g,
    const float* __restrict__ gg,  const float* __restrict__ beg, int l)
{
    const float* w1 = W1g + l * 4096;
    const float* w2 = W2g + l * 4096;
    for (int idx = tid; idx < 4096; idx += NTHR_) {
        int kq = idx >> 6, q = idx & 63;
        int src = dlog(kq) * 64 + dlog(q);
        dst[WOFF_W1 + idx] = w1[src];
        dst[WOFF_W2 + idx] = w2[src];
    }
    if (tid < 64) {
        dst[WOFF_B1 + tid] = b1g[l * 64 + dlog(tid)];
        dst[WOFF_B2 + tid] = b2g[l * 64 + dlog(tid)];
        dst[WOFF_G  + tid] = gg [l * 64 + tid];      // plain (used scalar)
        dst[WOFF_BE + tid] = beg[l * 64 + tid];      // plain
    }
}

__global__ void __launch_bounds__(NTHR_, 1) idmpnn_main(
    const int*   __restrict__ x,        // (B, NM, 1)
    const float* __restrict__ subadj,   // (B, NM, NM)
    const int*   __restrict__ subgs,    // (S, K)
    const int*   __restrict__ num_node, // (B,)
    const float* __restrict__ idemb,    // (5, 64)
    const float* __restrict__ node_emb, // (101, 64)
    const float* __restrict__ W1g, const float* __restrict__ b1g,
    const float* __restrict__ W2g, const float* __restrict__ b2g,
    const float* __restrict__ gg,  const float* __restrict__ beg,
    const float* __restrict__ s1W, const float* __restrict__ s1b,
    const float* __restrict__ s2W, const float* __restrict__ s2b)
{
    extern __shared__ float sm[];
    const int s    = blockIdx.x;
    const int b    = s >> 5;            // graph id (NS=32)
    const int tid  = threadIdx.x;
    const int warp = tid >> 5;
    const int lane = tid & 31;
    const int l2   = 2 * lane;          // physical base of this lane's pair

    // ---- adjacency (plain layout) ----
    if (tid < 256) {
        ((float4*)(sm + OFF_A))[tid] = ((const float4*)(subadj + b * 1024))[tid];
    }
    // ---- layer-0 weights ----
    load_layer_weights(sm + OFF_WB0, tid, W1g, b1g, W2g, b2g, gg, beg, 0);

    // ---- initial H (physical-interleaved dims) ----
    {
        const int sg0 = subgs[3 * s + 0];
        const int sg1 = subgs[3 * s + 1];
        const int sg2 = subgs[3 * s + 2];
        for (int e = tid; e < 12288; e += NTHR_) {
            int row  = e >> 6;          // row = node*6 + p
            int q    = e & 63;
            int node = row / 6;
            int p    = row - node * 6;
            int d    = dlog(q);
            float v = node_emb[x[b * 32 + node] * 64 + d];
            int k = (node == sg0) ? 0 : (node == sg1) ? 1 : (node == sg2) ? 2 : -1;
            if (k >= 0) v *= idemb[c_perm[p][k] * 64 + d];
            sm[OFF_HA + e] = v;
        }
    }
    __syncthreads();

    float* Ts = sm + OFF_TS + warp * 256;   // private 4x64 staging (interleaved)
    int srcO = OFF_HA, dstO = OFF_HB;

    // ================= layer loop =================
    for (int l = 0; l < NLAYER_; l++) {
        const float* W = sm + ((l & 1) ? OFF_WB1 : OFF_WB0);
        float* Wnext = sm + (((l + 1) & 1) ? OFF_WB1 : OFF_WB0);

        if (l < NLAYER_ - 1) {
            load_layer_weights(Wnext, tid, W1g, b1g, W2g, b2g, gg, beg, l + 1);
        } else {
            // set-MLP weights, same permutation
            for (int idx = tid; idx < 4096; idx += NTHR_) {
                int kq = idx >> 6, q = idx & 63;
                int src = dlog(kq) * 64 + dlog(q);
                Wnext[WOFF_W1 + idx] = s1W[src];
                Wnext[WOFF_W2 + idx] = s2W[src];
            }
            if (tid < 64) {
                Wnext[WOFF_B1 + tid] = s1b[dlog(tid)];
                Wnext[WOFF_B2 + tid] = s2b[dlog(tid)];
            }
        }

        const float* src = sm + srcO;
        float*       dst = sm + dstO;

        // 48 tasks of (perm p, 4-row block); 3 per warp; fused mp+MLP+LN+residual
        #pragma unroll
        for (int qid = 0; qid < 3; qid++) {
            const int t  = warp * 3 + qid;
            const int p  = t >> 3;
            const int i0 = (t & 7) * 4;

            // ---- m = A @ H (packed f32x2 accumulators) ----
            ull acc[4] = {0ull, 0ull, 0ull, 0ull};
            #pragma unroll
            for (int j = 0; j < 32; j += 4) {
                float4 av[4];
                #pragma unroll
                for (int r = 0; r < 4; r++)
                    av[r] = *(const float4*)&sm[OFF_A + (i0 + r) * 32 + j];
                #pragma unroll
                for (int jj = 0; jj < 4; jj++) {
                    ull hp = *(const ull*)&src[((j + jj) * 6 + p) * 64 + l2];
                    ffma2(acc[0], splat2(((const float*)&av[0])[jj]), hp);
                    ffma2(acc[1], splat2(((const float*)&av[1])[jj]), hp);
                    ffma2(acc[2], splat2(((const float*)&av[2])[jj]), hp);
                    ffma2(acc[3], splat2(((const float*)&av[3])[jj]), hp);
                }
            }
            #pragma unroll
            for (int r = 0; r < 4; r++)
                *(ull*)&Ts[r * 64 + l2] = acc[r];
            __syncwarp();

            // ---- MLP layer 1 ----
            ull a[4] = {0ull, 0ull, 0ull, 0ull};
            #pragma unroll
            for (int k = 0; k < 64; k += 4) {
                float4 mv[4];
                #pragma unroll
                for (int r = 0; r < 4; r++)
                    mv[r] = *(const float4*)&Ts[r * 64 + k];
                #pragma unroll
                for (int kk = 0; kk < 4; kk++) {
                    ull wp = *(const ull*)&W[WOFF_W1 + (k + kk) * 64 + l2];
                    ffma2(a[0], splat2(((const float*)&mv[0])[kk]), wp);
                    ffma2(a[1], splat2(((const float*)&mv[1])[kk]), wp);
                    ffma2(a[2], splat2(((const float*)&mv[2])[kk]), wp);
                    ffma2(a[3], splat2(((const float*)&mv[3])[kk]), wp);
                }
            }
            __syncwarp();
            {
                float2 b1p = *(const float2*)&W[WOFF_B1 + l2];
                #pragma unroll
                for (int r = 0; r < 4; r++) {
                    float2 v = unpk(a[r]);
                    Ts[r * 64 + l2]     = fmaxf(v.x + b1p.x, 0.f);
                    Ts[r * 64 + l2 + 1] = fmaxf(v.y + b1p.y, 0.f);
                }
            }
            __syncwarp();

            // ---- MLP layer 2 ----
            ull u[4] = {0ull, 0ull, 0ull, 0ull};
            #pragma unroll
            for (int k = 0; k < 64; k += 4) {
                float4 tv[4];
                #pragma unroll
                for (int r = 0; r < 4; r++)
                    tv[r] = *(const float4*)&Ts[r * 64 + k];
                #pragma unroll
                for (int kk = 0; kk < 4; kk++) {
                    ull wp = *(const ull*)&W[WOFF_W2 + (k + kk) * 64 + l2];
                    ffma2(u[0], splat2(((const float*)&tv[0])[kk]), wp);
                    ffma2(u[1], splat2(((const float*)&tv[1])[kk]), wp);
                    ffma2(u[2], splat2(((const float*)&tv[2])[kk]), wp);
                    ffma2(u[3], splat2(((const float*)&tv[3])[kk]), wp);
                }
            }
            __syncwarp();

            // ---- batched LayerNorm + relu + residual ----
            float z0[4], z1[4], sum[4];
            {
                float2 b2p = *(const float2*)&W[WOFF_B2 + l2];
                #pragma unroll
                for (int r = 0; r < 4; r++) {
                    float2 v = unpk(u[r]);
                    z0[r] = v.x + b2p.x;   // logical dim = lane
                    z1[r] = v.y + b2p.y;   // logical dim = lane+32
                    sum[r] = z0[r] + z1[r];
                }
            }
            #pragma unroll
            for (int o = 16; o; o >>= 1) {
                #pragma unroll
                for (int r = 0; r < 4; r++)
                    sum[r] += __shfl_xor_sync(0xffffffffu, sum[r], o);
            }
            float var[4];
            #pragma unroll
            for (int r = 0; r < 4; r++) {
                float mean = sum[r] * (1.f / 64.f);
                z0[r] -= mean; z1[r] -= mean;
                var[r] = z0[r] * z0[r] + z1[r] * z1[r];
            }
            #pragma unroll
            for (int o = 16; o; o >>= 1) {
                #pragma unroll
                for (int r = 0; r < 4; r++)
                    var[r] += __shfl_xor_sync(0xffffffffu, var[r], o);
            }
            #pragma unroll
            for (int r = 0; r < 4; r++) {
                float rstd = rsqrtf(var[r] * (1.f / 64.f) + 1e-5f);
                float o0 = fmaxf(z0[r] * rstd * W[WOFF_G + lane]      + W[WOFF_BE + lane],      0.f);
                float o1 = fmaxf(z1[r] * rstd * W[WOFF_G + lane + 32] + W[WOFF_BE + lane + 32], 0.f);
                int row = (i0 + r) * 6 + p;
                float2 sp = *(const float2*)&src[row * 64 + l2];
                float2 dp; dp.x = sp.x + o0; dp.y = sp.y + o1;
                *(float2*)&dst[row * 64 + l2] = dp;
            }
        }
        __syncthreads();
        int tmp = srcO; srcO = dstO; dstO = tmp;
    }
    // final H in HA; set weights (permuted) in WB0

    const float* Wset = sm + OFF_WB0;

    // zero padded-node rows
    {
        const int nn = num_node[b];
        for (int e = nn * 384 + tid; e < 12288; e += NTHR_) sm[OFF_HA + e] = 0.f;
    }
    __syncthreads();

    // mean over perms -> HB (physical layout preserved)
    for (int e = tid; e < 2048; e += NTHR_) {
        int i = e >> 6, q = e & 63;
        float acc = 0.f;
        #pragma unroll
        for (int p = 0; p < 6; p++) acc += sm[OFF_HA + i * 384 + p * 64 + q];
        sm[OFF_HB + e] = acc * (1.f / 6.f);
    }
    __syncthreads();

    // set1 MLP over 32 node rows (2 per warp) + node-sum partials
    {
        const int r0 = warp * 2;
        ull a[2] = {0ull, 0ull};
        #pragma unroll
        for (int k = 0; k < 64; k += 4) {
            float4 mv[2];
            #pragma unroll
            for (int r = 0; r < 2; r++)
                mv[r] = *(const float4*)&sm[OFF_HB + (r0 + r) * 64 + k];
            #pragma unroll
            for (int kk = 0; kk < 4; kk++) {
                ull wp = *(const ull*)&Wset[WOFF_W1 + (k + kk) * 64 + l2];
                ffma2(a[0], splat2(((const float*)&mv[0])[kk]), wp);
                ffma2(a[1], splat2(((const float*)&mv[1])[kk]), wp);
            }
        }
        float2 b1p = *(const float2*)&Wset[WOFF_B1 + l2];
        float p0 = 0.f, p1 = 0.f;
        #pragma unroll
        for (int r = 0; r < 2; r++) {
            float2 v = unpk(a[r]);
            p0 += fmaxf(v.x + b1p.x, 0.f);
            p1 += fmaxf(v.y + b1p.y, 0.f);
        }
        sm[OFF_TS + warp * 64 + l2]     = p0;
        sm[OFF_TS + warp * 64 + l2 + 1] = p1;
    }
    __syncthreads();
    if (tid < 64) {
        float ss = 0.f;
        #pragma unroll
        for (int w = 0; w < 16; w++) ss += sm[OFF_TS + w * 64 + tid];
        sm[OFF_SS + tid] = ss;   // physical order
    }
    __syncthreads();

    // set2 MLP on summed vector -> per-subgraph output (logical order to g_subg)
    if (warp == 0) {
        float a0 = 0.f, a1 = 0.f;
        #pragma unroll
        for (int q = 0; q < 64; q++) {
            float v = sm[OFF_SS + q];
            a0 += v * Wset[WOFF_W2 + q * 64 + l2];
            a1 += v * Wset[WOFF_W2 + q * 64 + l2 + 1];
        }
        float2 b2p = *(const float2*)&Wset[WOFF_B2 + l2];
        g_subg[s * 64 + lane]      = fmaxf(a0 + b2p.x, 0.f);
        g_subg[s * 64 + lane + 32] = fmaxf(a1 + b2p.y, 0.f);
    }
}

__global__ void __launch_bounds__(64, 1) finalize_k(
    const float* __restrict__ outW, const float* __restrict__ outb,
    float* __restrict__ out)
{
    const int b = blockIdx.x;
    const int d = threadIdx.x;
    float m = g_subg[(b * 32) * 64 + d];
    #pragma unroll
    for (int ss = 1; ss < 32; ss++)
        m = fmaxf(m, g_subg[(b * 32 + ss) * 64 + d]);
    float v = m * outW[d];
    #pragma unroll
    for (int o = 16; o; o >>= 1) v += __shfl_xor_sync(0xffffffffu, v, o);
    __shared__ float red[2];
    if ((d & 31) == 0) red[d >> 5] = v;
    __syncthreads();
    if (d == 0) out[b] = red[0] + red[1] + outb[0];
}

extern "C" void kernel_launch(void* const* d_in, const int* in_sizes, int n_in,
                              void* d_out, int out_size)
{
    const int*   x        = (const int*)  d_in[0];
    const float* subadj   = (const float*)d_in[1];
    const int*   subgs    = (const int*)  d_in[2];
    const int*   num_node = (const int*)  d_in[3];
    // d_in[4] = num_subg (unused)
    const float* idemb    = (const float*)d_in[5];
    const float* node_emb = (const float*)d_in[6];
    const float* W1       = (const float*)d_in[7];
    const float* b1       = (const float*)d_in[8];
    const float* W2       = (const float*)d_in[9];
    const float* b2       = (const float*)d_in[10];
    const float* g        = (const float*)d_in[11];
    const float* be       = (const float*)d_in[12];
    const float* s1W      = (const float*)d_in[13];
    const float* s1b      = (const float*)d_in[14];
    const float* s2W      = (const float*)d_in[15];
    const float* s2b      = (const float*)d_in[16];
    const float* outW     = (const float*)d_in[17];
    const float* outb     = (const float*)d_in[18];

    cudaFuncSetAttribute(idmpnn_main,
                         cudaFuncAttributeMaxDynamicSharedMemorySize, SMEM_BYTES);

    idmpnn_main<<<S_, NTHR_, SMEM_BYTES>>>(
        x, subadj, subgs, num_node, idemb, node_emb,
        W1, b1, W2, b2, g, be, s1W, s1b, s2W, s2b);
    finalize_k<<<B_, 64>>>(outW, outb, (float*)d_out);
}

// round 7
// speedup vs baseline: 2.4662x; 1.3189x over previous
#include <cuda_runtime.h>

// Problem constants
#define B_      64
#define NM_     32
#define NS_     32
#define K_      3
#define HID_    64
#define NLAYER_ 4
#define S_      2048     // B*NS
#define P_      6        // K!
#define ROWS_   192      // NM*P
#define NTHR_   512      // 16 warps

// itertools.permutations(range(3)); allperm[k][p] = c_perm[p][k]
__constant__ int c_perm[6][3] = {
    {0,1,2},{0,2,1},{1,0,2},{1,2,0},{2,0,1},{2,1,0}
};

// per-subgraph post-set2 vectors (S, 64) — logical dim order
__device__ float g_subg[S_ * HID_];

// ---- shared memory layout (floats) ----
// Feature dim stored PHYSICALLY INTERLEAVED: physical q holds logical
// d = (q>>1) + (q&1)*32, so lane L owns the packed pair at phys {2L, 2L+1}
// = logical {L, L+32}. Applies to H, Ts, W (N-cols), biases. Gamma/beta plain.
#define OFF_A    0                       // 32x32 adjacency        (1024)
#define OFF_HA   1024                    // H ping                 (12288)
#define OFF_HB   (OFF_HA + 12288)        // H pong                 (12288)
#define OFF_WB0  (OFF_HB + 12288)        // weight buffer 0        (8448)
#define OFF_WB1  (OFF_WB0 + 8448)        // weight buffer 1        (8448)
#define OFF_TS   (OFF_WB1 + 8448)        // per-warp staging 16x768 (12288)
#define OFF_SS   (OFF_TS + 12288)        // node-sum vector        (64)
#define SMEM_FLOATS (OFF_SS + 64)
#define SMEM_BYTES  (SMEM_FLOATS * 4)    // 219,392 B

// offsets inside a weight buffer (K-rows physically permuted, N-cols interleaved)
#define WOFF_W1  0
#define WOFF_W2  4096
#define WOFF_B1  8192
#define WOFF_B2  8256
#define WOFF_G   8320
#define WOFF_BE  8384

typedef unsigned long long ull;

__device__ __forceinline__ void ffma2(ull& d, ull a, ull b) {
    asm("fma.rn.f32x2 %0, %1, %2, %0;" : "+l"(d) : "l"(a), "l"(b));
}
__device__ __forceinline__ ull splat2(float v) {
    ull r;
    asm("mov.b64 %0, {%1, %1};" : "=l"(r) : "f"(v));
    return r;
}
__device__ __forceinline__ float2 unpk(ull v) {
    float2 f;
    asm("mov.b64 {%0, %1}, %2;" : "=f"(f.x), "=f"(f.y) : "l"(v));
    return f;
}
__device__ __forceinline__ int dlog(int q) { return (q >> 1) + ((q & 1) << 5); }

// load one layer's weights into smem, applying the interleave permutation:
//   dst[kq*64 + q] = W[dlog(kq)*64 + dlog(q)]
__device__ __forceinline__ void load_layer_weights(
    float* dst, int tid,
    const float* __restrict__ W1g, const float* __restrict__ b1g,
    const float* __restrict__ W2g, const float* __restrict__ b2g,
    const float* __restrict__ gg,  const float* __restrict__ beg, int l)
{
    const float* w1 = W1g + l * 4096;
    const float* w2 = W2g + l * 4096;
    for (int idx = tid; idx < 4096; idx += NTHR_) {
        int kq = idx >> 6, q = idx & 63;
        int src = dlog(kq) * 64 + dlog(q);
        dst[WOFF_W1 + idx] = w1[src];
        dst[WOFF_W2 + idx] = w2[src];
    }
    if (tid < 64) {
        dst[WOFF_B1 + tid] = b1g[l * 64 + dlog(tid)];
        dst[WOFF_B2 + tid] = b2g[l * 64 + dlog(tid)];
        dst[WOFF_G  + tid] = gg [l * 64 + tid];      // plain (used scalar)
        dst[WOFF_BE + tid] = beg[l * 64 + tid];      // plain
    }
}

__global__ void __launch_bounds__(NTHR_, 1) idmpnn_main(
    const int*   __restrict__ x,        // (B, NM, 1)
    const float* __restrict__ subadj,   // (B, NM, NM)
    const int*   __restrict__ subgs,    // (S, K)
    const int*   __restrict__ num_node, // (B,)
    const float* __restrict__ idemb,    // (5, 64)
    const float* __restrict__ node_emb, // (101, 64)
    const float* __restrict__ W1g, const float* __restrict__ b1g,
    const float* __restrict__ W2g, const float* __restrict__ b2g,
    const float* __restrict__ gg,  const float* __restrict__ beg,
    const float* __restrict__ s1W, const float* __restrict__ s1b,
    const float* __restrict__ s2W, const float* __restrict__ s2b)
{
    extern __shared__ float sm[];
    const int s    = blockIdx.x;
    const int b    = s >> 5;            // graph id (NS=32)
    const int tid  = threadIdx.x;
    const int warp = tid >> 5;
    const int lane = tid & 31;
    const int l2   = 2 * lane;          // physical base of this lane's pair

    // ---- adjacency (plain layout) ----
    if (tid < 256) {
        ((float4*)(sm + OFF_A))[tid] = ((const float4*)(subadj + b * 1024))[tid];
    }
    // ---- layer-0 weights ----
    load_layer_weights(sm + OFF_WB0, tid, W1g, b1g, W2g, b2g, gg, beg, 0);

    // ---- initial H (physical-interleaved dims) ----
    {
        const int sg0 = subgs[3 * s + 0];
        const int sg1 = subgs[3 * s + 1];
        const int sg2 = subgs[3 * s + 2];
        for (int e = tid; e < 12288; e += NTHR_) {
            int row  = e >> 6;          // row = node*6 + p
            int q    = e & 63;
            int node = row / 6;
            int p    = row - node * 6;
            int d    = dlog(q);
            float v = node_emb[x[b * 32 + node] * 64 + d];
            int k = (node == sg0) ? 0 : (node == sg1) ? 1 : (node == sg2) ? 2 : -1;
            if (k >= 0) v *= idemb[c_perm[p][k] * 64 + d];
            sm[OFF_HA + e] = v;
        }
    }
    __syncthreads();

    // warp-private 12x64 staging
    float* Tw = sm + OFF_TS + warp * 768;

    // this warp's 12 rows (3 tasks x 4 rows)
    const int t0 = warp * 3;
    int iRow[12], rowg[12], pArr[3];
    #pragma unroll
    for (int q = 0; q < 3; q++) {
        int t = t0 + q;
        int p = t >> 3;
        int i0 = (t & 7) * 4;
        pArr[q] = p;
        #pragma unroll
        for (int r = 0; r < 4; r++) {
            iRow[q * 4 + r] = i0 + r;
            rowg[q * 4 + r] = (i0 + r) * 6 + p;
        }
    }
    const bool unip = (pArr[0] == pArr[2]);

    int srcO = OFF_HA, dstO = OFF_HB;

    // ================= layer loop =================
    for (int l = 0; l < NLAYER_; l++) {
        const float* W = sm + ((l & 1) ? OFF_WB1 : OFF_WB0);
        float* Wnext = sm + (((l + 1) & 1) ? OFF_WB1 : OFF_WB0);

        if (l < NLAYER_ - 1) {
            load_layer_weights(Wnext, tid, W1g, b1g, W2g, b2g, gg, beg, l + 1);
        } else {
            // set-MLP weights, same permutation
            for (int idx = tid; idx < 4096; idx += NTHR_) {
                int kq = idx >> 6, q = idx & 63;
                int src = dlog(kq) * 64 + dlog(q);
                Wnext[WOFF_W1 + idx] = s1W[src];
                Wnext[WOFF_W2 + idx] = s2W[src];
            }
            if (tid < 64) {
                Wnext[WOFF_B1 + tid] = s1b[dlog(tid)];
                Wnext[WOFF_B2 + tid] = s2b[dlog(tid)];
            }
        }

        const float* src = sm + srcO;
        float*       dst = sm + dstO;

        // ---- phase A: m = A @ H for 12 rows (packed f32x2 accumulators) ----
        ull acc[12];
        #pragma unroll
        for (int u = 0; u < 12; u++) acc[u] = 0ull;

        if (unip) {
            const int p0 = pArr[0];
            #pragma unroll
            for (int j = 0; j < 32; j += 4) {
                float4 av[12];
                #pragma unroll
                for (int u = 0; u < 12; u++)
                    av[u] = *(const float4*)&sm[OFF_A + iRow[u] * 32 + j];
                #pragma unroll
                for (int jj = 0; jj < 4; jj++) {
                    ull hp = *(const ull*)&src[((j + jj) * 6 + p0) * 64 + l2];
                    #pragma unroll
                    for (int u = 0; u < 12; u++)
                        ffma2(acc[u], splat2(((const float*)&av[u])[jj]), hp);
                }
            }
        } else {
            #pragma unroll
            for (int j = 0; j < 32; j += 4) {
                float4 av[12];
                #pragma unroll
                for (int u = 0; u < 12; u++)
                    av[u] = *(const float4*)&sm[OFF_A + iRow[u] * 32 + j];
                #pragma unroll
                for (int jj = 0; jj < 4; jj++) {
                    ull hpq[3];
                    #pragma unroll
                    for (int q = 0; q < 3; q++)
                        hpq[q] = *(const ull*)&src[((j + jj) * 6 + pArr[q]) * 64 + l2];
                    #pragma unroll
                    for (int q = 0; q < 3; q++)
                        #pragma unroll
                        for (int r = 0; r < 4; r++)
                            ffma2(acc[q * 4 + r],
                                  splat2(((const float*)&av[q * 4 + r])[jj]), hpq[q]);
                }
            }
        }
        #pragma unroll
        for (int u = 0; u < 12; u++)
            *(ull*)&Tw[u * 64 + l2] = acc[u];
        __syncwarp();

        // ---- MLP layer 1 (W pair loaded once per k for all 12 rows) ----
        ull a[12];
        #pragma unroll
        for (int u = 0; u < 12; u++) a[u] = 0ull;
        #pragma unroll
        for (int k = 0; k < 64; k += 4) {
            float4 mv[12];
            #pragma unroll
            for (int u = 0; u < 12; u++)
                mv[u] = *(const float4*)&Tw[u * 64 + k];
            #pragma unroll
            for (int kk = 0; kk < 4; kk++) {
                ull wp = *(const ull*)&W[WOFF_W1 + (k + kk) * 64 + l2];
                #pragma unroll
                for (int u = 0; u < 12; u++)
                    ffma2(a[u], splat2(((const float*)&mv[u])[kk]), wp);
            }
        }
        __syncwarp();
        {
            float2 b1p = *(const float2*)&W[WOFF_B1 + l2];
            #pragma unroll
            for (int u = 0; u < 12; u++) {
                float2 v = unpk(a[u]);
                Tw[u * 64 + l2]     = fmaxf(v.x + b1p.x, 0.f);
                Tw[u * 64 + l2 + 1] = fmaxf(v.y + b1p.y, 0.f);
            }
        }
        __syncwarp();

        // ---- MLP layer 2 ----
        ull u2[12];
        #pragma unroll
        for (int u = 0; u < 12; u++) u2[u] = 0ull;
        #pragma unroll
        for (int k = 0; k < 64; k += 4) {
            float4 tv[12];
            #pragma unroll
            for (int u = 0; u < 12; u++)
                tv[u] = *(const float4*)&Tw[u * 64 + k];
            #pragma unroll
            for (int kk = 0; kk < 4; kk++) {
                ull wp = *(const ull*)&W[WOFF_W2 + (k + kk) * 64 + l2];
                #pragma unroll
                for (int u = 0; u < 12; u++)
                    ffma2(u2[u], splat2(((const float*)&tv[u])[kk]), wp);
            }
        }
        __syncwarp();

        // ---- batched LayerNorm + relu + residual (12 rows, ILP shuffles) ----
        {
            float z0[12], z1[12], sum[12];
            float2 b2p = *(const float2*)&W[WOFF_B2 + l2];
            #pragma unroll
            for (int u = 0; u < 12; u++) {
                float2 v = unpk(u2[u]);
                z0[u] = v.x + b2p.x;   // logical dim = lane
                z1[u] = v.y + b2p.y;   // logical dim = lane+32
                sum[u] = z0[u] + z1[u];
            }
            #pragma unroll
            for (int o = 16; o; o >>= 1) {
                #pragma unroll
                for (int u = 0; u < 12; u++)
                    sum[u] += __shfl_xor_sync(0xffffffffu, sum[u], o);
            }
            float var[12];
            #pragma unroll
            for (int u = 0; u < 12; u++) {
                float mean = sum[u] * (1.f / 64.f);
                z0[u] -= mean; z1[u] -= mean;
                var[u] = z0[u] * z0[u] + z1[u] * z1[u];
            }
            #pragma unroll
            for (int o = 16; o; o >>= 1) {
                #pragma unroll
                for (int u = 0; u < 12; u++)
                    var[u] += __shfl_xor_sync(0xffffffffu, var[u], o);
            }
            float gl0 = W[WOFF_G + lane],  gl1 = W[WOFF_G + lane + 32];
            float bl0 = W[WOFF_BE + lane], bl1 = W[WOFF_BE + lane + 32];
            #pragma unroll
            for (int u = 0; u < 12; u++) {
                float rstd = rsqrtf(var[u] * (1.f / 64.f) + 1e-5f);
                float o0 = fmaxf(z0[u] * rstd * gl0 + bl0, 0.f);
                float o1 = fmaxf(z1[u] * rstd * gl1 + bl1, 0.f);
                int row = rowg[u];
                float2 sp = *(const float2*)&src[row * 64 + l2];
                float2 dp; dp.x = sp.x + o0; dp.y = sp.y + o1;
                *(float2*)&dst[row * 64 + l2] = dp;
            }
        }
        __syncthreads();
        int tmp = srcO; srcO = dstO; dstO = tmp;
    }
    // final H in HA; set weights (permuted) in WB0

    const float* Wset = sm + OFF_WB0;

    // zero padded-node rows
    {
        const int nn = num_node[b];
        for (int e = nn * 384 + tid; e < 12288; e += NTHR_) sm[OFF_HA + e] = 0.f;
    }
    __syncthreads();

    // mean over perms -> HB (physical layout preserved)
    for (int e = tid; e < 2048; e += NTHR_) {
        int i = e >> 6, q = e & 63;
        float acc = 0.f;
        #pragma unroll
        for (int p = 0; p < 6; p++) acc += sm[OFF_HA + i * 384 + p * 64 + q];
        sm[OFF_HB + e] = acc * (1.f / 6.f);
    }
    __syncthreads();

    // set1 MLP over 32 node rows (2 per warp) + node-sum partials
    {
        const int r0 = warp * 2;
        ull a[2] = {0ull, 0ull};
        #pragma unroll
        for (int k = 0; k < 64; k += 4) {
            float4 mv[2];
            #pragma unroll
            for (int r = 0; r < 2; r++)
                mv[r] = *(const float4*)&sm[OFF_HB + (r0 + r) * 64 + k];
            #pragma unroll
            for (int kk = 0; kk < 4; kk++) {
                ull wp = *(const ull*)&Wset[WOFF_W1 + (k + kk) * 64 + l2];
                ffma2(a[0], splat2(((const float*)&mv[0])[kk]), wp);
                ffma2(a[1], splat2(((const float*)&mv[1])[kk]), wp);
            }
        }
        float2 b1p = *(const float2*)&Wset[WOFF_B1 + l2];
        float p0 = 0.f, p1 = 0.f;
        #pragma unroll
        for (int r = 0; r < 2; r++) {
            float2 v = unpk(a[r]);
            p0 += fmaxf(v.x + b1p.x, 0.f);
            p1 += fmaxf(v.y + b1p.y, 0.f);
        }
        sm[OFF_TS + warp * 64 + l2]     = p0;
        sm[OFF_TS + warp * 64 + l2 + 1] = p1;
    }
    __syncthreads();
    if (tid < 64) {
        float ss = 0.f;
        #pragma unroll
        for (int w = 0; w < 16; w++) ss += sm[OFF_TS + w * 64 + tid];
        sm[OFF_SS + tid] = ss;   // physical order
    }
    __syncthreads();

    // set2 MLP on summed vector -> per-subgraph output (logical order to g_subg)
    if (warp == 0) {
        float a0 = 0.f, a1 = 0.f;
        #pragma unroll
        for (int q = 0; q < 64; q++) {
            float v = sm[OFF_SS + q];
            a0 += v * Wset[WOFF_W2 + q * 64 + l2];
            a1 += v * Wset[WOFF_W2 + q * 64 + l2 + 1];
        }
        float2 b2p = *(const float2*)&Wset[WOFF_B2 + l2];
        g_subg[s * 64 + lane]      = fmaxf(a0 + b2p.x, 0.f);
        g_subg[s * 64 + lane + 32] = fmaxf(a1 + b2p.y, 0.f);
    }
}

__global__ void __launch_bounds__(64, 1) finalize_k(
    const float* __restrict__ outW, const float* __restrict__ outb,
    float* __restrict__ out)
{
    const int b = blockIdx.x;
    const int d = threadIdx.x;
    float m = g_subg[(b * 32) * 64 + d];
    #pragma unroll
    for (int ss = 1; ss < 32; ss++)
        m = fmaxf(m, g_subg[(b * 32 + ss) * 64 + d]);
    float v = m * outW[d];
    #pragma unroll
    for (int o = 16; o; o >>= 1) v += __shfl_xor_sync(0xffffffffu, v, o);
    __shared__ float red[2];
    if ((d & 31) == 0) red[d >> 5] = v;
    __syncthreads();
    if (d == 0) out[b] = red[0] + red[1] + outb[0];
}

extern "C" void kernel_launch(void* const* d_in, const int* in_sizes, int n_in,
                              void* d_out, int out_size)
{
    const int*   x        = (const int*)  d_in[0];
    const float* subadj   = (const float*)d_in[1];
    const int*   subgs    = (const int*)  d_in[2];
    const int*   num_node = (const int*)  d_in[3];
    // d_in[4] = num_subg (unused)
    const float* idemb    = (const float*)d_in[5];
    const float* node_emb = (const float*)d_in[6];
    const float* W1       = (const float*)d_in[7];
    const float* b1       = (const float*)d_in[8];
    const float* W2       = (const float*)d_in[9];
    const float* b2       = (const float*)d_in[10];
    const float* g        = (const float*)d_in[11];
    const float* be       = (const float*)d_in[12];
    const float* s1W      = (const float*)d_in[13];
    const float* s1b      = (const float*)d_in[14];
    const float* s2W      = (const float*)d_in[15];
    const float* s2b      = (const float*)d_in[16];
    const float* outW     = (const float*)d_in[17];
    const float* outb     = (const float*)d_in[18];

    cudaFuncSetAttribute(idmpnn_main,
                         cudaFuncAttributeMaxDynamicSharedMemorySize, SMEM_BYTES);

    idmpnn_main<<<S_, NTHR_, SMEM_BYTES>>>(
        x, subadj, subgs, num_node, idemb, node_emb,
        W1, b1, W2, b2, g, be, s1W, s1b, s2W, s2b);
    finalize_k<<<B_, 64>>>(outW, outb, (float*)d_out);
}